// round 14
// baseline (speedup 1.0000x reference)
#include <cuda_runtime.h>
#include <cuda_bf16.h>
#include <cuda_fp16.h>
#include <stdint.h>
#include <math.h>

// ---------------------------------------------------------------------------
// Mamba2-style SSD block. Round 11: GEMM CTA tile 256x128 with 64x64 warp
// tiles (crossbar traffic x0.68). Rest unchanged from R10 (1080us).
// ---------------------------------------------------------------------------

#define S_LEN   4096
#define DIM_    2048
#define HID_    4096
#define D_IN_   8512
#define D_INP_  8576
#define CONVD_  4352
#define NH_     64
#define HD_     64
#define NST_    128
#define CH_     256
#define NC_     16

__device__ float g_zx[(size_t)S_LEN * D_IN_];
__device__ float g_conv[(size_t)S_LEN * CONVD_];
__device__ float g_dt[S_LEN * NH_];
__device__ float g_dAc[S_LEN * NH_];
__device__ float g_CB[NC_ * CH_ * CH_];
__device__ float g_states[NC_ * NH_ * HD_ * NST_];
__device__ float g_prev[NC_ * NH_ * HD_ * NST_];
__device__ float g_y[(size_t)S_LEN * HID_];

__device__ __half g_xh[(size_t)S_LEN * DIM_];
__device__ __half g_wih[(size_t)D_INP_ * DIM_];
__device__ __half g_yh[(size_t)S_LEN * HID_];
__device__ __half g_woh[(size_t)DIM_ * HID_];

// ---------------------------------------------------------------------------
__device__ __forceinline__ uint32_t su32(const void* p) {
    uint32_t a;
    asm("{ .reg .u64 t; cvta.to.shared.u64 t, %1; cvt.u32.u64 %0, t; }"
        : "=r"(a) : "l"(p));
    return a;
}

__device__ __forceinline__ void cpasync16(uint32_t dst, const void* src) {
    asm volatile("cp.async.cg.shared.global [%0], [%1], 16;" :: "r"(dst), "l"(src));
}
#define CP_COMMIT() asm volatile("cp.async.commit_group;" ::: "memory")
#define CP_WAIT1()  asm volatile("cp.async.wait_group 1;" ::: "memory")

#define LDSM4(r, addr) \
    asm volatile("ldmatrix.sync.aligned.m8n8.x4.shared.b16 {%0,%1,%2,%3}, [%4];" \
        : "=r"((r)[0]), "=r"((r)[1]), "=r"((r)[2]), "=r"((r)[3]) : "r"(addr))

#define LDSM4T(r, addr) \
    asm volatile("ldmatrix.sync.aligned.m8n8.x4.trans.shared.b16 {%0,%1,%2,%3}, [%4];" \
        : "=r"((r)[0]), "=r"((r)[1]), "=r"((r)[2]), "=r"((r)[3]) : "r"(addr))

#define MMA16816H(d, a, b0, b1) \
    asm volatile("mma.sync.aligned.m16n8k16.row.col.f32.f16.f16.f32 " \
        "{%0,%1,%2,%3}, {%4,%5,%6,%7}, {%8,%9}, {%0,%1,%2,%3};" \
        : "+f"((d)[0]), "+f"((d)[1]), "+f"((d)[2]), "+f"((d)[3]) \
        : "r"((a)[0]), "r"((a)[1]), "r"((a)[2]), "r"((a)[3]), "r"(b0), "r"(b1))

__device__ __forceinline__ uint32_t pack2h(float a, float b) {
    __half2 H = __halves2half2(__float2half_rn(a), __float2half_rn(b));
    return *(uint32_t*)&H;
}

// ---------------------------------------------------------------------------
// fp16 single-pass GEMM: C[M,N] = Ah[M,K] @ Bh[Npad,K]^T
// 256x128 CTA, BK=64, 2-stage double buffer, 256 threads,
// 8 warps at 4(M)x2(N), each warp 64x64.
// ---------------------------------------------------------------------------
#define PAD_K       72
#define A_BYTES     (256 * PAD_K * 2)       // 36864
#define B_BYTES     (128 * PAD_K * 2)       // 18432
#define STAGE_BYTES (A_BYTES + B_BYTES)     // 55296
#define GM_SMEM_TOTAL (2 * STAGE_BYTES)     // 110592

__global__ __launch_bounds__(256, 1) void gemm_mma(
    const __half* __restrict__ Ah, const __half* __restrict__ Bh,
    float* __restrict__ C, int N, int K)
{
    extern __shared__ char smem[];
    const uint32_t sb = su32(smem);
    const int tid = threadIdx.x;
    const int lane = tid & 31;
    const int warp = tid >> 5;
    const int warpM = warp >> 1;         // 0..3 -> m offset *64
    const int warpN = warp & 1;          // 0..1 -> n offset *64
    const int m0 = blockIdx.y * 256, n0 = blockIdx.x * 128;

    float acc[4][8][4];
#pragma unroll
    for (int i = 0; i < 4; i++)
#pragma unroll
        for (int j = 0; j < 8; j++)
#pragma unroll
            for (int v = 0; v < 4; v++) acc[i][j][v] = 0.f;

    auto load_chunk = [&](int i, int s) {
        const size_t k0 = (size_t)i * 64;
        const uint32_t st = sb + s * STAGE_BYTES;
        // A: 256 rows x 8 segs = 2048 ops, 8 per thread
#pragma unroll
        for (int t = 0; t < 8; t++) {
            const int idx = t * 256 + tid;
            const int r = idx >> 3;
            const int cs = idx & 7;
            cpasync16(st + (uint32_t)(r * PAD_K + cs * 8) * 2,
                      Ah + (size_t)(m0 + r) * K + k0 + cs * 8);
        }
        // B: 128 rows x 8 segs = 1024 ops, 4 per thread
#pragma unroll
        for (int t = 0; t < 4; t++) {
            const int idx = t * 256 + tid;
            const int r = idx >> 3;
            const int cs = idx & 7;
            cpasync16(st + A_BYTES + (uint32_t)(r * PAD_K + cs * 8) * 2,
                      Bh + (size_t)(n0 + r) * K + k0 + cs * 8);
        }
    };

    const int nch = K >> 6;
    load_chunk(0, 0); CP_COMMIT();
    load_chunk(1, 1); CP_COMMIT();

    const int lr = lane & 15;
    const int lc8 = (lane >> 4) * 8;

    for (int i = 0; i < nch; i++) {
        const int s = i & 1;
        CP_WAIT1();
        __syncthreads();

        const uint32_t aB = sb + s * STAGE_BYTES;
        const uint32_t bB = aB + A_BYTES;
#pragma unroll
        for (int k16 = 0; k16 < 4; k16++) {
            const int kof = k16 * 16 + lc8;
            uint32_t a[4][4];
#pragma unroll
            for (int mt = 0; mt < 4; mt++) {
                const uint32_t ad = aB + (uint32_t)((warpM * 64 + mt * 16 + lr) * PAD_K + kof) * 2;
                LDSM4(a[mt], ad);
            }
            uint32_t b[4][4];
#pragma unroll
            for (int ng = 0; ng < 4; ng++) {
                const uint32_t bd = bB + (uint32_t)((warpN * 64 + ng * 16 + lr) * PAD_K + kof) * 2;
                LDSM4(b[ng], bd);
            }
#pragma unroll
            for (int mt = 0; mt < 4; mt++)
#pragma unroll
                for (int nt = 0; nt < 8; nt++) {
                    const int ng = nt >> 1, sel = nt & 1;
                    MMA16816H(acc[mt][nt], a[mt], b[ng][sel], b[ng][sel + 2]);
                }
        }
        __syncthreads();
        if (i + 2 < nch) load_chunk(i + 2, s);
        CP_COMMIT();
    }

#pragma unroll
    for (int mt = 0; mt < 4; mt++) {
        const int row = m0 + warpM * 64 + mt * 16 + (lane >> 2);
#pragma unroll
        for (int nt = 0; nt < 8; nt++) {
            const int col = n0 + warpN * 64 + nt * 8 + (lane & 3) * 2;
            if (col < N) {
                *(float2*)&C[(size_t)row * N + col] =
                    make_float2(acc[mt][nt][0], acc[mt][nt][1]);
                *(float2*)&C[(size_t)(row + 8) * N + col] =
                    make_float2(acc[mt][nt][2], acc[mt][nt][3]);
            }
        }
    }
}

// fp32 -> fp16 single round; zero-pads beyond n4_src
__global__ void round_f16(const float* __restrict__ src,
                          __half* __restrict__ hi, int n4_src, int n4_tot)
{
    const int i = blockIdx.x * blockDim.x + threadIdx.x;
    if (i >= n4_tot) return;
    float4 v = make_float4(0.f, 0.f, 0.f, 0.f);
    if (i < n4_src) v = ((const float4*)src)[i];
    ((uint32_t*)hi)[2 * i] = pack2h(v.x, v.y);
    ((uint32_t*)hi)[2 * i + 1] = pack2h(v.z, v.w);
}

// ---------------------------------------------------------------------------
// fp32 tiled SGEMM (small CB batch only): C = A @ B^T
// ---------------------------------------------------------------------------
__global__ __launch_bounds__(256) void gemm128(
    int M, int N, int K,
    const float* __restrict__ A, int lda, int strideA,
    const float* __restrict__ B, int ldb, int strideB,
    float* __restrict__ C, int ldc, int strideC)
{
    __shared__ float As[8 * 128];
    __shared__ float Bs[8 * 128];
    const int bz = blockIdx.z;
    A += (size_t)bz * strideA;
    B += (size_t)bz * strideB;
    C += (size_t)bz * strideC;
    const int m0 = blockIdx.y * 128;
    const int n0 = blockIdx.x * 128;
    const int tid = threadIdx.x;
    const int lrow = tid >> 1;
    const int lseg = (tid & 1) * 4;
    const int ty = tid >> 4;
    const int tx = tid & 15;

    float acc[8][8];
#pragma unroll
    for (int i = 0; i < 8; i++)
#pragma unroll
        for (int j = 0; j < 8; j++) acc[i][j] = 0.f;

    const float* aptr = A + (size_t)(m0 + lrow) * lda + lseg;
    const float* bptr = B + (size_t)(n0 + lrow) * ldb + lseg;

    for (int k0 = 0; k0 < K; k0 += 8) {
        float4 a4 = *(const float4*)(aptr + k0);
        float4 b4 = *(const float4*)(bptr + k0);
        As[(lseg + 0) * 128 + lrow] = a4.x;
        As[(lseg + 1) * 128 + lrow] = a4.y;
        As[(lseg + 2) * 128 + lrow] = a4.z;
        As[(lseg + 3) * 128 + lrow] = a4.w;
        Bs[(lseg + 0) * 128 + lrow] = b4.x;
        Bs[(lseg + 1) * 128 + lrow] = b4.y;
        Bs[(lseg + 2) * 128 + lrow] = b4.z;
        Bs[(lseg + 3) * 128 + lrow] = b4.w;
        __syncthreads();
#pragma unroll
        for (int k = 0; k < 8; k++) {
            float ar[8], br[8];
            *(float4*)&ar[0] = *(const float4*)&As[k * 128 + ty * 8];
            *(float4*)&ar[4] = *(const float4*)&As[k * 128 + ty * 8 + 4];
            *(float4*)&br[0] = *(const float4*)&Bs[k * 128 + tx * 8];
            *(float4*)&br[4] = *(const float4*)&Bs[k * 128 + tx * 8 + 4];
#pragma unroll
            for (int i = 0; i < 8; i++)
#pragma unroll
                for (int j = 0; j < 8; j++)
                    acc[i][j] = fmaf(ar[i], br[j], acc[i][j]);
        }
        __syncthreads();
    }

#pragma unroll
    for (int i = 0; i < 8; i++) {
        const int m = m0 + ty * 8 + i;
#pragma unroll
        for (int j4 = 0; j4 < 8; j4 += 4) {
            const int n = n0 + tx * 8 + j4;
            *(float4*)(C + (size_t)m * ldc + n) =
                make_float4(acc[i][j4], acc[i][j4 + 1], acc[i][j4 + 2], acc[i][j4 + 3]);
        }
    }
}

// ---------------------------------------------------------------------------
// conv1d + SiLU: 8 timesteps x 4 channels per thread, rolling window
// ---------------------------------------------------------------------------
#define CT_T 8
__global__ void conv_silu_kernel(const float* __restrict__ w)
{
    const int idx = blockIdx.x * blockDim.x + threadIdx.x;
    const int NQ = CONVD_ / 4;
    if (idx >= (S_LEN / CT_T) * NQ) return;
    const int c4 = idx % NQ;
    const int t0 = (idx / NQ) * CT_T;

    const float4 w0 = *(const float4*)&w[(c4 * 4 + 0) * 4];
    const float4 w1 = *(const float4*)&w[(c4 * 4 + 1) * 4];
    const float4 w2 = *(const float4*)&w[(c4 * 4 + 2) * 4];
    const float4 w3 = *(const float4*)&w[(c4 * 4 + 3) * 4];

    float4 win[4] = {make_float4(0.f, 0.f, 0.f, 0.f), make_float4(0.f, 0.f, 0.f, 0.f),
                     make_float4(0.f, 0.f, 0.f, 0.f), make_float4(0.f, 0.f, 0.f, 0.f)};
#pragma unroll
    for (int i = 0; i < CT_T + 3; i++) {
        const int row = t0 - 3 + i;
        float4 xv = make_float4(0.f, 0.f, 0.f, 0.f);
        if (row >= 0)
            xv = *(const float4*)&g_zx[(size_t)row * D_IN_ + HID_ + c4 * 4];
        win[0] = win[1]; win[1] = win[2]; win[2] = win[3]; win[3] = xv;
        if (i >= 3) {
            float4 a;
            a.x = win[0].x * w0.x + win[1].x * w0.y + win[2].x * w0.z + win[3].x * w0.w;
            a.y = win[0].y * w1.x + win[1].y * w1.y + win[2].y * w1.z + win[3].y * w1.w;
            a.z = win[0].z * w2.x + win[1].z * w2.y + win[2].z * w2.z + win[3].z * w2.w;
            a.w = win[0].w * w3.x + win[1].w * w3.y + win[2].w * w3.z + win[3].w * w3.w;
            float4 o;
            o.x = a.x / (1.f + __expf(-a.x));
            o.y = a.y / (1.f + __expf(-a.y));
            o.z = a.z / (1.f + __expf(-a.z));
            o.w = a.w / (1.f + __expf(-a.w));
            *(float4*)&g_conv[(size_t)(t0 + i - 3) * CONVD_ + c4 * 4] = o;
        }
    }
}

__global__ void dt_kernel(const float* __restrict__ dt_bias,
                          const float* __restrict__ A_log)
{
    const int idx = blockIdx.x * blockDim.x + threadIdx.x;
    if (idx >= S_LEN * NH_) return;
    const int h = idx % NH_;
    const int t = idx / NH_;
    const float raw = g_zx[(size_t)t * D_IN_ + (HID_ + CONVD_) + h] + dt_bias[h];
    const float dt = (raw > 20.f) ? raw : log1pf(__expf(raw));
    g_dt[idx] = dt;
    g_dAc[idx] = dt * (-__expf(A_log[h]));
}

__global__ __launch_bounds__(CH_) void cumsum_kernel()
{
    const int c = blockIdx.x, h = blockIdx.y;
    const int l = threadIdx.x;
    __shared__ float sbuf[CH_];
    const int gi = (c * CH_ + l) * NH_ + h;
    sbuf[l] = g_dAc[gi];
    __syncthreads();
    for (int off = 1; off < CH_; off <<= 1) {
        const float add = (l >= off) ? sbuf[l - off] : 0.f;
        __syncthreads();
        sbuf[l] += add;
        __syncthreads();
    }
    g_dAc[gi] = sbuf[l];
}

// ---------------------------------------------------------------------------
// states via single-pass fp16 mma (unchanged from R10)
// ---------------------------------------------------------------------------
__global__ __launch_bounds__(256) void states_mma()
{
    const int c = blockIdx.x, h = blockIdx.y;
    __shared__ float sdec[CH_];
    __shared__ __half sA[32 * 72];
    __shared__ __half sB[32 * 136];
    const int tid = threadIdx.x;
    const int lane = tid & 31, warp = tid >> 5;
    const int warpM = warp & 1, warpN = warp >> 1;

    {
        const float dalast = g_dAc[(c * CH_ + CH_ - 1) * NH_ + h];
        const int gi = (c * CH_ + tid) * NH_ + h;
        sdec[tid] = g_dt[gi] * __expf(dalast - g_dAc[gi]);
    }
    __syncthreads();

    float acc[2][4][4];
#pragma unroll
    for (int i = 0; i < 2; i++)
#pragma unroll
        for (int j = 0; j < 4; j++)
#pragma unroll
            for (int v = 0; v < 4; v++) acc[i][j][v] = 0.f;

    const int krA = (lane & 7) | ((lane >> 4) << 3);
    const int mbA = ((lane >> 3) & 1) * 8;
    const int krB = (lane & 7) | (((lane >> 3) & 1) << 3);
    const int nbB = (lane >> 4) * 8;

    for (int s0 = 0; s0 < CH_; s0 += 32) {
#pragma unroll
        for (int t = 0; t < 2; t++) {
            const int gi = t * 256 + tid;
            const int row = gi >> 4, p4 = (gi & 15) * 4;
            const float wv = sdec[s0 + row];
            float4 v = *(const float4*)&g_conv[(size_t)(c * CH_ + s0 + row) * CONVD_ + h * HD_ + p4];
            uint32_t* d_ = (uint32_t*)&sA[row * 72 + p4];
            d_[0] = pack2h(v.x * wv, v.y * wv);
            d_[1] = pack2h(v.z * wv, v.w * wv);
        }
#pragma unroll
        for (int t = 0; t < 4; t++) {
            const int gi = t * 256 + tid;
            const int row = gi >> 5, n4 = (gi & 31) * 4;
            float4 v = *(const float4*)&g_conv[(size_t)(c * CH_ + s0 + row) * CONVD_ + HID_ + n4];
            uint32_t* d_ = (uint32_t*)&sB[row * 136 + n4];
            d_[0] = pack2h(v.x, v.y);
            d_[1] = pack2h(v.z, v.w);
        }
        __syncthreads();
#pragma unroll
        for (int k16 = 0; k16 < 2; k16++) {
            uint32_t a[2][4];
#pragma unroll
            for (int mt = 0; mt < 2; mt++) {
                const int mc = warpM * 32 + mt * 16 + mbA;
                LDSM4T(a[mt], su32(&sA[(k16 * 16 + krA) * 72 + mc]));
            }
            uint32_t b[4][2];
#pragma unroll
            for (int nh2 = 0; nh2 < 2; nh2++) {
                const int nc = warpN * 32 + nh2 * 16 + nbB;
                uint32_t r[4];
                LDSM4T(r, su32(&sB[(k16 * 16 + krB) * 136 + nc]));
                b[nh2 * 2][0] = r[0]; b[nh2 * 2][1] = r[1];
                b[nh2 * 2 + 1][0] = r[2]; b[nh2 * 2 + 1][1] = r[3];
            }
#pragma unroll
            for (int mt = 0; mt < 2; mt++)
#pragma unroll
                for (int ng = 0; ng < 4; ng++)
                    MMA16816H(acc[mt][ng], a[mt], b[ng][0], b[ng][1]);
        }
        __syncthreads();
    }

    const size_t base = ((size_t)(c * NH_ + h)) * HD_ * NST_;
#pragma unroll
    for (int mt = 0; mt < 2; mt++) {
        const int row = warpM * 32 + mt * 16 + (lane >> 2);
#pragma unroll
        for (int ng = 0; ng < 4; ng++) {
            const int col = warpN * 32 + ng * 8 + (lane & 3) * 2;
            *(float2*)&g_states[base + (size_t)row * NST_ + col] =
                make_float2(acc[mt][ng][0], acc[mt][ng][1]);
            *(float2*)&g_states[base + (size_t)(row + 8) * NST_ + col] =
                make_float2(acc[mt][ng][2], acc[mt][ng][3]);
        }
    }
}

__global__ void chunkscan_kernel()
{
    const int idx = blockIdx.x * blockDim.x + threadIdx.x;
    if (idx >= NH_ * HD_ * NST_) return;
    const int h = idx / (HD_ * NST_);
    const int rem = idx % (HD_ * NST_);
    float carry = 0.f;
#pragma unroll
    for (int c = 0; c < NC_; c++) {
        const size_t off = ((size_t)(c * NH_ + h)) * HD_ * NST_ + rem;
        g_prev[off] = carry;
        const float dec = __expf(g_dAc[(c * CH_ + CH_ - 1) * NH_ + h]);
        carry = carry * dec + g_states[off];
    }
}

// ---------------------------------------------------------------------------
// ydiag via single-pass fp16 mma (unchanged from R10)
// ---------------------------------------------------------------------------
#define YD_M 0
#define YD_X 2560
#define YD_C 0
#define YD_P 4608

__global__ __launch_bounds__(256) void ydiag_mma(const float* __restrict__ Dp)
{
    const int lt = blockIdx.x, c = blockIdx.y, h = blockIdx.z;
    __shared__ float sdAc[CH_], sdtv[CH_];
    __shared__ __half sbuf[9216];
    const int tid = threadIdx.x;
    const int lane = tid & 31, warp = tid >> 5;
    const int warpM = warp & 1, warpN = warp >> 1;
    const int l0 = lt * 64;

    {
        const int gi = (c * CH_ + tid) * NH_ + h;
        sdAc[tid] = g_dAc[gi];
        sdtv[tid] = g_dt[gi];
    }
    __syncthreads();

    float accA[2][2][4], acc2[2][2][4];
#pragma unroll
    for (int i = 0; i < 2; i++)
#pragma unroll
        for (int j = 0; j < 2; j++)
#pragma unroll
            for (int v = 0; v < 4; v++) { accA[i][j][v] = 0.f; acc2[i][j][v] = 0.f; }

    const int lr = lane & 15;
    const int lc8 = (lane >> 4) * 8;
    const int krB = (lane & 7) | (((lane >> 3) & 1) << 3);
    const int nbB = (lane >> 4) * 8;

    const int smax = l0 + 64;
    for (int s0 = 0; s0 < smax; s0 += 32) {
        {
            const int lrow = tid >> 2;
            const int sseg = (tid & 3) * 8;
            const float dacl = sdAc[l0 + lrow];
            const float* cbp = &g_CB[c * (CH_ * CH_) + (l0 + lrow) * CH_ + s0 + sseg];
            float4 cb0 = *(const float4*)cbp;
            float4 cb1 = *(const float4*)(cbp + 4);
            float cbv[8] = {cb0.x, cb0.y, cb0.z, cb0.w, cb1.x, cb1.y, cb1.z, cb1.w};
#pragma unroll
            for (int j = 0; j < 8; j++) {
                const int s = s0 + sseg + j;
                float v = 0.f;
                if (s <= l0 + lrow) v = cbv[j] * __expf(dacl - sdAc[s]);
                sbuf[YD_M + lrow * 40 + sseg + j] = __float2half_rn(v);
            }
        }
#pragma unroll
        for (int t = 0; t < 2; t++) {
            const int gi = t * 256 + tid;
            const int row = gi >> 4, p4 = (gi & 15) * 4;
            const float wv = sdtv[s0 + row];
            float4 v = *(const float4*)&g_conv[(size_t)(c * CH_ + s0 + row) * CONVD_ + h * HD_ + p4];
            uint32_t* d_ = (uint32_t*)&sbuf[YD_X + row * 72 + p4];
            d_[0] = pack2h(v.x * wv, v.y * wv);
            d_[1] = pack2h(v.z * wv, v.w * wv);
        }
        __syncthreads();
#pragma unroll
        for (int k16 = 0; k16 < 2; k16++) {
            uint32_t a[2][4];
#pragma unroll
            for (int mt = 0; mt < 2; mt++)
                LDSM4(a[mt], su32(&sbuf[YD_M + (warpM * 32 + mt * 16 + lr) * 40 + k16 * 16 + lc8]));
            uint32_t b[2][2];
            {
                const int nc = warpN * 16 + nbB;
                uint32_t r[4];
                LDSM4T(r, su32(&sbuf[YD_X + (k16 * 16 + krB) * 72 + nc]));
                b[0][0] = r[0]; b[0][1] = r[1]; b[1][0] = r[2]; b[1][1] = r[3];
            }
#pragma unroll
            for (int mt = 0; mt < 2; mt++)
#pragma unroll
                for (int ng = 0; ng < 2; ng++)
                    MMA16816H(accA[mt][ng], a[mt], b[ng][0], b[ng][1]);
        }
        __syncthreads();
    }

    const size_t pbase = ((size_t)(c * NH_ + h)) * HD_ * NST_;
    for (int n0c = 0; n0c < NST_; n0c += 64) {
#pragma unroll
        for (int t = 0; t < 4; t++) {
            const int gi = t * 256 + tid;
            const int row = gi >> 4, n4 = (gi & 15) * 4;
            float4 v = *(const float4*)&g_conv[(size_t)(c * CH_ + l0 + row) * CONVD_ +
                                               HID_ + NST_ + n0c + n4];
            uint32_t* d_ = (uint32_t*)&sbuf[YD_C + row * 72 + n4];
            d_[0] = pack2h(v.x, v.y);
            d_[1] = pack2h(v.z, v.w);

            float4 p = *(const float4*)&g_prev[pbase + (size_t)row * NST_ + n0c + n4];
            uint32_t* p_ = (uint32_t*)&sbuf[YD_P + row * 72 + n4];
            p_[0] = pack2h(p.x, p.y);
            p_[1] = pack2h(p.z, p.w);
        }
        __syncthreads();
#pragma unroll
        for (int k16 = 0; k16 < 4; k16++) {
            uint32_t a[2][4];
#pragma unroll
            for (int mt = 0; mt < 2; mt++)
                LDSM4(a[mt], su32(&sbuf[YD_C + (warpM * 32 + mt * 16 + lr) * 72 + k16 * 16 + lc8]));
            uint32_t b[4];
            LDSM4(b, su32(&sbuf[YD_P + (warpN * 16 + lr) * 72 + k16 * 16 + lc8]));
#pragma unroll
            for (int mt = 0; mt < 2; mt++)
#pragma unroll
                for (int ng = 0; ng < 2; ng++)
                    MMA16816H(acc2[mt][ng], a[mt], b[ng], b[ng + 2]);
        }
        __syncthreads();
    }

    const float dh = Dp[h];
#pragma unroll
    for (int mt = 0; mt < 2; mt++) {
        const int lrow = warpM * 32 + mt * 16 + (lane >> 2);
#pragma unroll
        for (int ng = 0; ng < 2; ng++) {
            const int col = warpN * 16 + ng * 8 + (lane & 3) * 2;
#pragma unroll
            for (int half = 0; half < 2; half++) {
                const int l = l0 + lrow + half * 8;
                const int t = c * CH_ + l;
                const float el = __expf(sdAc[l]);
                const float2 x2 = *(const float2*)&g_conv[(size_t)t * CONVD_ + h * HD_ + col];
                float2 o;
                o.x = accA[mt][ng][half * 2]     + el * acc2[mt][ng][half * 2]     + x2.x * dh;
                o.y = accA[mt][ng][half * 2 + 1] + el * acc2[mt][ng][half * 2 + 1] + x2.y * dh;
                *(float2*)&g_y[(size_t)t * HID_ + h * HD_ + col] = o;
            }
        }
    }
}

// ---------------------------------------------------------------------------
// gate + RMSNorm, fused fp16 output for out_proj
// ---------------------------------------------------------------------------
__global__ __launch_bounds__(256) void gatenorm_kernel(const float* __restrict__ nw)
{
    const int t = blockIdx.x;
    const int tid = threadIdx.x;
    float vals[16];
    float ss = 0.f;
#pragma unroll
    for (int k = 0; k < 16; k++) {
        const int i = tid + k * 256;
        const float yv = g_y[(size_t)t * HID_ + i];
        const float zv = g_zx[(size_t)t * D_IN_ + i];
        const float v = yv * (zv / (1.f + __expf(-zv)));
        vals[k] = v;
        ss += v * v;
    }
    __shared__ float red[8];
#pragma unroll
    for (int o = 16; o > 0; o >>= 1) ss += __shfl_xor_sync(0xffffffffu, ss, o);
    if ((tid & 31) == 0) red[tid >> 5] = ss;
    __syncthreads();
    if (tid < 8) {
        float v = red[tid];
#pragma unroll
        for (int o = 4; o > 0; o >>= 1) v += __shfl_xor_sync(0xffu, v, o);
        if (tid == 0) red[0] = v;
    }
    __syncthreads();
    const float scale = rsqrtf(red[0] / (float)HID_ + 1e-5f);
#pragma unroll
    for (int k = 0; k < 16; k++) {
        const int i = tid + k * 256;
        g_yh[(size_t)t * HID_ + i] = __float2half_rn(vals[k] * scale * nw[i]);
    }
}

// ---------------------------------------------------------------------------
extern "C" void kernel_launch(void* const* d_in, const int* in_sizes, int n_in,
                              void* d_out, int out_size)
{
    const float* x       = (const float*)d_in[0];
    const float* in_w    = (const float*)d_in[1];
    const float* conv_w  = (const float*)d_in[2];
    const float* dt_bias = (const float*)d_in[3];
    const float* A_log   = (const float*)d_in[4];
    const float* Dp      = (const float*)d_in[5];
    const float* norm_w  = (const float*)d_in[6];
    const float* out_w   = (const float*)d_in[7];
    float* out = (float*)d_out;

    float *zx, *conv, *cb;
    __half *xh, *wih, *yh, *woh;
    cudaGetSymbolAddress((void**)&zx, g_zx);
    cudaGetSymbolAddress((void**)&conv, g_conv);
    cudaGetSymbolAddress((void**)&cb, g_CB);
    cudaGetSymbolAddress((void**)&xh, g_xh);
    cudaGetSymbolAddress((void**)&wih, g_wih);
    cudaGetSymbolAddress((void**)&yh, g_yh);
    cudaGetSymbolAddress((void**)&woh, g_woh);

    cudaFuncSetAttribute(gemm_mma, cudaFuncAttributeMaxDynamicSharedMemorySize,
                         GM_SMEM_TOTAL);

    // 0) fp16 rounds for in_proj operands
    {
        const int n4s = S_LEN * DIM_ / 4;
        round_f16<<<(n4s + 255) / 256, 256>>>(x, xh, n4s, n4s);
        const int n4w = D_IN_ * DIM_ / 4;
        const int n4wt = D_INP_ * DIM_ / 4;
        round_f16<<<(n4wt + 255) / 256, 256>>>(in_w, wih, n4w, n4wt);
    }

    // 1) in_proj: M=4096, N=8512 (B padded to 8576)
    gemm_mma<<<dim3(D_INP_ / 128, S_LEN / 256), 256, GM_SMEM_TOTAL>>>(
        xh, wih, zx, D_IN_, DIM_);

    // 2) conv1d + SiLU (time-tiled)
    conv_silu_kernel<<<((S_LEN / CT_T) * (CONVD_ / 4) + 255) / 256, 256>>>(conv_w);

    // 3) dt / dA
    dt_kernel<<<(S_LEN * NH_ + 255) / 256, 256>>>(dt_bias, A_log);

    // 4) cumsum
    cumsum_kernel<<<dim3(NC_, NH_), CH_>>>();

    // 5) CB per chunk
    gemm128<<<dim3(2, 2, NC_), 256>>>(
        CH_, CH_, NST_,
        conv + HID_ + NST_, CONVD_, CH_ * CONVD_,
        conv + HID_,        CONVD_, CH_ * CONVD_,
        cb, CH_, CH_ * CH_);

    // 6) states (fp16 mma)
    states_mma<<<dim3(NC_, NH_), 256>>>();

    // 7) inter-chunk scan
    chunkscan_kernel<<<(NH_ * HD_ * NST_) / 256, 256>>>();

    // 8) y_diag + y_off + D-skip (fp16 mma)
    ydiag_mma<<<dim3(4, NC_, NH_), 256>>>(Dp);

    // 9) gate + RMSNorm (+ fused fp16 round)
    gatenorm_kernel<<<S_LEN, 256>>>(norm_w);

    // 10) out_proj: M=4096, N=2048
    {
        const int n4o = DIM_ * HID_ / 4;
        round_f16<<<(n4o + 255) / 256, 256>>>(out_w, woh, n4o, n4o);
    }
    gemm_mma<<<dim3(DIM_ / 128, S_LEN / 256), 256, GM_SMEM_TOTAL>>>(
        yh, woh, out, DIM_, HID_);
}

// round 15
// speedup vs baseline: 1.1085x; 1.1085x over previous
#include <cuda_runtime.h>
#include <cuda_bf16.h>
#include <cuda_fp16.h>
#include <stdint.h>
#include <math.h>

// ---------------------------------------------------------------------------
// Mamba2-style SSD block. Round 12: revert GEMM to R10 128x128/BK=64 config
// (256x128 spilled), add __launch_bounds__(256,2) for 2 CTAs/SM latency
// hiding; fuse dt into cumsum. Rest unchanged from R10 (1080us).
// ---------------------------------------------------------------------------

#define S_LEN   4096
#define DIM_    2048
#define HID_    4096
#define D_IN_   8512
#define D_INP_  8576
#define CONVD_  4352
#define NH_     64
#define HD_     64
#define NST_    128
#define CH_     256
#define NC_     16

__device__ float g_zx[(size_t)S_LEN * D_IN_];
__device__ float g_conv[(size_t)S_LEN * CONVD_];
__device__ float g_dt[S_LEN * NH_];
__device__ float g_dAc[S_LEN * NH_];
__device__ float g_CB[NC_ * CH_ * CH_];
__device__ float g_states[NC_ * NH_ * HD_ * NST_];
__device__ float g_prev[NC_ * NH_ * HD_ * NST_];
__device__ float g_y[(size_t)S_LEN * HID_];

__device__ __half g_xh[(size_t)S_LEN * DIM_];
__device__ __half g_wih[(size_t)D_INP_ * DIM_];
__device__ __half g_yh[(size_t)S_LEN * HID_];
__device__ __half g_woh[(size_t)DIM_ * HID_];

// ---------------------------------------------------------------------------
__device__ __forceinline__ uint32_t su32(const void* p) {
    uint32_t a;
    asm("{ .reg .u64 t; cvta.to.shared.u64 t, %1; cvt.u32.u64 %0, t; }"
        : "=r"(a) : "l"(p));
    return a;
}

__device__ __forceinline__ void cpasync16(uint32_t dst, const void* src) {
    asm volatile("cp.async.cg.shared.global [%0], [%1], 16;" :: "r"(dst), "l"(src));
}
#define CP_COMMIT() asm volatile("cp.async.commit_group;" ::: "memory")
#define CP_WAIT1()  asm volatile("cp.async.wait_group 1;" ::: "memory")

#define LDSM4(r, addr) \
    asm volatile("ldmatrix.sync.aligned.m8n8.x4.shared.b16 {%0,%1,%2,%3}, [%4];" \
        : "=r"((r)[0]), "=r"((r)[1]), "=r"((r)[2]), "=r"((r)[3]) : "r"(addr))

#define LDSM4T(r, addr) \
    asm volatile("ldmatrix.sync.aligned.m8n8.x4.trans.shared.b16 {%0,%1,%2,%3}, [%4];" \
        : "=r"((r)[0]), "=r"((r)[1]), "=r"((r)[2]), "=r"((r)[3]) : "r"(addr))

#define MMA16816H(d, a, b0, b1) \
    asm volatile("mma.sync.aligned.m16n8k16.row.col.f32.f16.f16.f32 " \
        "{%0,%1,%2,%3}, {%4,%5,%6,%7}, {%8,%9}, {%0,%1,%2,%3};" \
        : "+f"((d)[0]), "+f"((d)[1]), "+f"((d)[2]), "+f"((d)[3]) \
        : "r"((a)[0]), "r"((a)[1]), "r"((a)[2]), "r"((a)[3]), "r"(b0), "r"(b1))

__device__ __forceinline__ uint32_t pack2h(float a, float b) {
    __half2 H = __halves2half2(__float2half_rn(a), __float2half_rn(b));
    return *(uint32_t*)&H;
}

// ---------------------------------------------------------------------------
// fp16 single-pass GEMM: C[M,N] = Ah[M,K] @ Bh[Npad,K]^T
// 128x128 CTA, BK=64, 2-stage double buffer, 256 threads, warps 4(M)x2(N).
// __launch_bounds__(256,2): target 2 CTAs/SM (regs capped at 128).
// ---------------------------------------------------------------------------
#define PAD_K       72
#define SUB_BYTES   (128 * PAD_K * 2)
#define STAGE_BYTES (2 * SUB_BYTES)
#define GM_SMEM_TOTAL (2 * STAGE_BYTES)

__global__ __launch_bounds__(256, 2) void gemm_mma(
    const __half* __restrict__ Ah, const __half* __restrict__ Bh,
    float* __restrict__ C, int N, int K)
{
    extern __shared__ char smem[];
    const uint32_t sb = su32(smem);
    const int tid = threadIdx.x;
    const int lane = tid & 31;
    const int warp = tid >> 5;
    const int warpM = warp & 3;
    const int warpN = warp >> 2;
    const int m0 = blockIdx.y * 128, n0 = blockIdx.x * 128;

    float acc[2][8][4];
#pragma unroll
    for (int i = 0; i < 2; i++)
#pragma unroll
        for (int j = 0; j < 8; j++)
#pragma unroll
            for (int v = 0; v < 4; v++) acc[i][j][v] = 0.f;

    auto load_chunk = [&](int i, int s) {
        const size_t k0 = (size_t)i * 64;
#pragma unroll
        for (int t = 0; t < 8; t++) {
            const int idx = t * 256 + tid;
            const int sub = idx >> 10;
            const int r = (idx >> 3) & 127;
            const int cs = idx & 7;
            const uint32_t d = sb + s * STAGE_BYTES + sub * SUB_BYTES
                             + (uint32_t)(r * PAD_K + cs * 8) * 2;
            const __half* bp = (sub == 0) ? Ah : Bh;
            const int rg = (sub == 0) ? (m0 + r) : (n0 + r);
            cpasync16(d, bp + (size_t)rg * K + k0 + cs * 8);
        }
    };

    const int nch = K >> 6;
    load_chunk(0, 0); CP_COMMIT();
    load_chunk(1, 1); CP_COMMIT();

    const int lr = lane & 15;
    const int lc8 = (lane >> 4) * 8;

    for (int i = 0; i < nch; i++) {
        const int s = i & 1;
        CP_WAIT1();
        __syncthreads();

        const uint32_t aB = sb + s * STAGE_BYTES;
        const uint32_t bB = aB + SUB_BYTES;
#pragma unroll
        for (int k16 = 0; k16 < 4; k16++) {
            const int kof = k16 * 16 + lc8;
            uint32_t a[2][4];
#pragma unroll
            for (int mt = 0; mt < 2; mt++) {
                const uint32_t ad = aB + (uint32_t)((warpM * 32 + mt * 16 + lr) * PAD_K + kof) * 2;
                LDSM4(a[mt], ad);
            }
            uint32_t b[4][4];
#pragma unroll
            for (int ng = 0; ng < 4; ng++) {
                const uint32_t bd = bB + (uint32_t)((warpN * 64 + ng * 16 + lr) * PAD_K + kof) * 2;
                LDSM4(b[ng], bd);
            }
#pragma unroll
            for (int mt = 0; mt < 2; mt++)
#pragma unroll
                for (int nt = 0; nt < 8; nt++) {
                    const int ng = nt >> 1, sel = nt & 1;
                    MMA16816H(acc[mt][nt], a[mt], b[ng][sel], b[ng][sel + 2]);
                }
        }
        __syncthreads();
        if (i + 2 < nch) load_chunk(i + 2, s);
        CP_COMMIT();
    }

#pragma unroll
    for (int mt = 0; mt < 2; mt++) {
        const int row = m0 + warpM * 32 + mt * 16 + (lane >> 2);
#pragma unroll
        for (int nt = 0; nt < 8; nt++) {
            const int col = n0 + warpN * 64 + nt * 8 + (lane & 3) * 2;
            if (col < N) {
                *(float2*)&C[(size_t)row * N + col] =
                    make_float2(acc[mt][nt][0], acc[mt][nt][1]);
                *(float2*)&C[(size_t)(row + 8) * N + col] =
                    make_float2(acc[mt][nt][2], acc[mt][nt][3]);
            }
        }
    }
}

// fp32 -> fp16 single round; zero-pads beyond n4_src
__global__ void round_f16(const float* __restrict__ src,
                          __half* __restrict__ hi, int n4_src, int n4_tot)
{
    const int i = blockIdx.x * blockDim.x + threadIdx.x;
    if (i >= n4_tot) return;
    float4 v = make_float4(0.f, 0.f, 0.f, 0.f);
    if (i < n4_src) v = ((const float4*)src)[i];
    ((uint32_t*)hi)[2 * i] = pack2h(v.x, v.y);
    ((uint32_t*)hi)[2 * i + 1] = pack2h(v.z, v.w);
}

// ---------------------------------------------------------------------------
// fp32 tiled SGEMM (small CB batch only): C = A @ B^T
// ---------------------------------------------------------------------------
__global__ __launch_bounds__(256) void gemm128(
    int M, int N, int K,
    const float* __restrict__ A, int lda, int strideA,
    const float* __restrict__ B, int ldb, int strideB,
    float* __restrict__ C, int ldc, int strideC)
{
    __shared__ float As[8 * 128];
    __shared__ float Bs[8 * 128];
    const int bz = blockIdx.z;
    A += (size_t)bz * strideA;
    B += (size_t)bz * strideB;
    C += (size_t)bz * strideC;
    const int m0 = blockIdx.y * 128;
    const int n0 = blockIdx.x * 128;
    const int tid = threadIdx.x;
    const int lrow = tid >> 1;
    const int lseg = (tid & 1) * 4;
    const int ty = tid >> 4;
    const int tx = tid & 15;

    float acc[8][8];
#pragma unroll
    for (int i = 0; i < 8; i++)
#pragma unroll
        for (int j = 0; j < 8; j++) acc[i][j] = 0.f;

    const float* aptr = A + (size_t)(m0 + lrow) * lda + lseg;
    const float* bptr = B + (size_t)(n0 + lrow) * ldb + lseg;

    for (int k0 = 0; k0 < K; k0 += 8) {
        float4 a4 = *(const float4*)(aptr + k0);
        float4 b4 = *(const float4*)(bptr + k0);
        As[(lseg + 0) * 128 + lrow] = a4.x;
        As[(lseg + 1) * 128 + lrow] = a4.y;
        As[(lseg + 2) * 128 + lrow] = a4.z;
        As[(lseg + 3) * 128 + lrow] = a4.w;
        Bs[(lseg + 0) * 128 + lrow] = b4.x;
        Bs[(lseg + 1) * 128 + lrow] = b4.y;
        Bs[(lseg + 2) * 128 + lrow] = b4.z;
        Bs[(lseg + 3) * 128 + lrow] = b4.w;
        __syncthreads();
#pragma unroll
        for (int k = 0; k < 8; k++) {
            float ar[8], br[8];
            *(float4*)&ar[0] = *(const float4*)&As[k * 128 + ty * 8];
            *(float4*)&ar[4] = *(const float4*)&As[k * 128 + ty * 8 + 4];
            *(float4*)&br[0] = *(const float4*)&Bs[k * 128 + tx * 8];
            *(float4*)&br[4] = *(const float4*)&Bs[k * 128 + tx * 8 + 4];
#pragma unroll
            for (int i = 0; i < 8; i++)
#pragma unroll
                for (int j = 0; j < 8; j++)
                    acc[i][j] = fmaf(ar[i], br[j], acc[i][j]);
        }
        __syncthreads();
    }

#pragma unroll
    for (int i = 0; i < 8; i++) {
        const int m = m0 + ty * 8 + i;
#pragma unroll
        for (int j4 = 0; j4 < 8; j4 += 4) {
            const int n = n0 + tx * 8 + j4;
            *(float4*)(C + (size_t)m * ldc + n) =
                make_float4(acc[i][j4], acc[i][j4 + 1], acc[i][j4 + 2], acc[i][j4 + 3]);
        }
    }
}

// ---------------------------------------------------------------------------
// conv1d + SiLU: 8 timesteps x 4 channels per thread, rolling window
// ---------------------------------------------------------------------------
#define CT_T 8
__global__ void conv_silu_kernel(const float* __restrict__ w)
{
    const int idx = blockIdx.x * blockDim.x + threadIdx.x;
    const int NQ = CONVD_ / 4;
    if (idx >= (S_LEN / CT_T) * NQ) return;
    const int c4 = idx % NQ;
    const int t0 = (idx / NQ) * CT_T;

    const float4 w0 = *(const float4*)&w[(c4 * 4 + 0) * 4];
    const float4 w1 = *(const float4*)&w[(c4 * 4 + 1) * 4];
    const float4 w2 = *(const float4*)&w[(c4 * 4 + 2) * 4];
    const float4 w3 = *(const float4*)&w[(c4 * 4 + 3) * 4];

    float4 win[4] = {make_float4(0.f, 0.f, 0.f, 0.f), make_float4(0.f, 0.f, 0.f, 0.f),
                     make_float4(0.f, 0.f, 0.f, 0.f), make_float4(0.f, 0.f, 0.f, 0.f)};
#pragma unroll
    for (int i = 0; i < CT_T + 3; i++) {
        const int row = t0 - 3 + i;
        float4 xv = make_float4(0.f, 0.f, 0.f, 0.f);
        if (row >= 0)
            xv = *(const float4*)&g_zx[(size_t)row * D_IN_ + HID_ + c4 * 4];
        win[0] = win[1]; win[1] = win[2]; win[2] = win[3]; win[3] = xv;
        if (i >= 3) {
            float4 a;
            a.x = win[0].x * w0.x + win[1].x * w0.y + win[2].x * w0.z + win[3].x * w0.w;
            a.y = win[0].y * w1.x + win[1].y * w1.y + win[2].y * w1.z + win[3].y * w1.w;
            a.z = win[0].z * w2.x + win[1].z * w2.y + win[2].z * w2.z + win[3].z * w2.w;
            a.w = win[0].w * w3.x + win[1].w * w3.y + win[2].w * w3.z + win[3].w * w3.w;
            float4 o;
            o.x = a.x / (1.f + __expf(-a.x));
            o.y = a.y / (1.f + __expf(-a.y));
            o.z = a.z / (1.f + __expf(-a.z));
            o.w = a.w / (1.f + __expf(-a.w));
            *(float4*)&g_conv[(size_t)(t0 + i - 3) * CONVD_ + c4 * 4] = o;
        }
    }
}

// ---------------------------------------------------------------------------
// fused dt (softplus) + per-chunk inclusive cumsum of dA
// ---------------------------------------------------------------------------
__global__ __launch_bounds__(CH_) void dtcumsum_kernel(
    const float* __restrict__ dt_bias, const float* __restrict__ A_log)
{
    const int c = blockIdx.x, h = blockIdx.y;
    const int l = threadIdx.x;
    __shared__ float sbuf[CH_];
    const int t = c * CH_ + l;
    const float raw = g_zx[(size_t)t * D_IN_ + (HID_ + CONVD_) + h] + dt_bias[h];
    const float dt = (raw > 20.f) ? raw : log1pf(__expf(raw));
    g_dt[t * NH_ + h] = dt;
    sbuf[l] = dt * (-__expf(A_log[h]));
    __syncthreads();
    for (int off = 1; off < CH_; off <<= 1) {
        const float add = (l >= off) ? sbuf[l - off] : 0.f;
        __syncthreads();
        sbuf[l] += add;
        __syncthreads();
    }
    g_dAc[t * NH_ + h] = sbuf[l];
}

// ---------------------------------------------------------------------------
// states via single-pass fp16 mma (unchanged from R10)
// ---------------------------------------------------------------------------
__global__ __launch_bounds__(256) void states_mma()
{
    const int c = blockIdx.x, h = blockIdx.y;
    __shared__ float sdec[CH_];
    __shared__ __half sA[32 * 72];
    __shared__ __half sB[32 * 136];
    const int tid = threadIdx.x;
    const int lane = tid & 31, warp = tid >> 5;
    const int warpM = warp & 1, warpN = warp >> 1;

    {
        const float dalast = g_dAc[(c * CH_ + CH_ - 1) * NH_ + h];
        const int gi = (c * CH_ + tid) * NH_ + h;
        sdec[tid] = g_dt[gi] * __expf(dalast - g_dAc[gi]);
    }
    __syncthreads();

    float acc[2][4][4];
#pragma unroll
    for (int i = 0; i < 2; i++)
#pragma unroll
        for (int j = 0; j < 4; j++)
#pragma unroll
            for (int v = 0; v < 4; v++) acc[i][j][v] = 0.f;

    const int krA = (lane & 7) | ((lane >> 4) << 3);
    const int mbA = ((lane >> 3) & 1) * 8;
    const int krB = (lane & 7) | (((lane >> 3) & 1) << 3);
    const int nbB = (lane >> 4) * 8;

    for (int s0 = 0; s0 < CH_; s0 += 32) {
#pragma unroll
        for (int t = 0; t < 2; t++) {
            const int gi = t * 256 + tid;
            const int row = gi >> 4, p4 = (gi & 15) * 4;
            const float wv = sdec[s0 + row];
            float4 v = *(const float4*)&g_conv[(size_t)(c * CH_ + s0 + row) * CONVD_ + h * HD_ + p4];
            uint32_t* d_ = (uint32_t*)&sA[row * 72 + p4];
            d_[0] = pack2h(v.x * wv, v.y * wv);
            d_[1] = pack2h(v.z * wv, v.w * wv);
        }
#pragma unroll
        for (int t = 0; t < 4; t++) {
            const int gi = t * 256 + tid;
            const int row = gi >> 5, n4 = (gi & 31) * 4;
            float4 v = *(const float4*)&g_conv[(size_t)(c * CH_ + s0 + row) * CONVD_ + HID_ + n4];
            uint32_t* d_ = (uint32_t*)&sB[row * 136 + n4];
            d_[0] = pack2h(v.x, v.y);
            d_[1] = pack2h(v.z, v.w);
        }
        __syncthreads();
#pragma unroll
        for (int k16 = 0; k16 < 2; k16++) {
            uint32_t a[2][4];
#pragma unroll
            for (int mt = 0; mt < 2; mt++) {
                const int mc = warpM * 32 + mt * 16 + mbA;
                LDSM4T(a[mt], su32(&sA[(k16 * 16 + krA) * 72 + mc]));
            }
            uint32_t b[4][2];
#pragma unroll
            for (int nh2 = 0; nh2 < 2; nh2++) {
                const int nc = warpN * 32 + nh2 * 16 + nbB;
                uint32_t r[4];
                LDSM4T(r, su32(&sB[(k16 * 16 + krB) * 136 + nc]));
                b[nh2 * 2][0] = r[0]; b[nh2 * 2][1] = r[1];
                b[nh2 * 2 + 1][0] = r[2]; b[nh2 * 2 + 1][1] = r[3];
            }
#pragma unroll
            for (int mt = 0; mt < 2; mt++)
#pragma unroll
                for (int ng = 0; ng < 4; ng++)
                    MMA16816H(acc[mt][ng], a[mt], b[ng][0], b[ng][1]);
        }
        __syncthreads();
    }

    const size_t base = ((size_t)(c * NH_ + h)) * HD_ * NST_;
#pragma unroll
    for (int mt = 0; mt < 2; mt++) {
        const int row = warpM * 32 + mt * 16 + (lane >> 2);
#pragma unroll
        for (int ng = 0; ng < 4; ng++) {
            const int col = warpN * 32 + ng * 8 + (lane & 3) * 2;
            *(float2*)&g_states[base + (size_t)row * NST_ + col] =
                make_float2(acc[mt][ng][0], acc[mt][ng][1]);
            *(float2*)&g_states[base + (size_t)(row + 8) * NST_ + col] =
                make_float2(acc[mt][ng][2], acc[mt][ng][3]);
        }
    }
}

__global__ void chunkscan_kernel()
{
    const int idx = blockIdx.x * blockDim.x + threadIdx.x;
    if (idx >= NH_ * HD_ * NST_) return;
    const int h = idx / (HD_ * NST_);
    const int rem = idx % (HD_ * NST_);
    float carry = 0.f;
#pragma unroll
    for (int c = 0; c < NC_; c++) {
        const size_t off = ((size_t)(c * NH_ + h)) * HD_ * NST_ + rem;
        g_prev[off] = carry;
        const float dec = __expf(g_dAc[(c * CH_ + CH_ - 1) * NH_ + h]);
        carry = carry * dec + g_states[off];
    }
}

// ---------------------------------------------------------------------------
// ydiag via single-pass fp16 mma (unchanged from R10)
// ---------------------------------------------------------------------------
#define YD_M 0
#define YD_X 2560
#define YD_C 0
#define YD_P 4608

__global__ __launch_bounds__(256) void ydiag_mma(const float* __restrict__ Dp)
{
    const int lt = blockIdx.x, c = blockIdx.y, h = blockIdx.z;
    __shared__ float sdAc[CH_], sdtv[CH_];
    __shared__ __half sbuf[9216];
    const int tid = threadIdx.x;
    const int lane = tid & 31, warp = tid >> 5;
    const int warpM = warp & 1, warpN = warp >> 1;
    const int l0 = lt * 64;

    {
        const int gi = (c * CH_ + tid) * NH_ + h;
        sdAc[tid] = g_dAc[gi];
        sdtv[tid] = g_dt[gi];
    }
    __syncthreads();

    float accA[2][2][4], acc2[2][2][4];
#pragma unroll
    for (int i = 0; i < 2; i++)
#pragma unroll
        for (int j = 0; j < 2; j++)
#pragma unroll
            for (int v = 0; v < 4; v++) { accA[i][j][v] = 0.f; acc2[i][j][v] = 0.f; }

    const int lr = lane & 15;
    const int lc8 = (lane >> 4) * 8;
    const int krB = (lane & 7) | (((lane >> 3) & 1) << 3);
    const int nbB = (lane >> 4) * 8;

    const int smax = l0 + 64;
    for (int s0 = 0; s0 < smax; s0 += 32) {
        {
            const int lrow = tid >> 2;
            const int sseg = (tid & 3) * 8;
            const float dacl = sdAc[l0 + lrow];
            const float* cbp = &g_CB[c * (CH_ * CH_) + (l0 + lrow) * CH_ + s0 + sseg];
            float4 cb0 = *(const float4*)cbp;
            float4 cb1 = *(const float4*)(cbp + 4);
            float cbv[8] = {cb0.x, cb0.y, cb0.z, cb0.w, cb1.x, cb1.y, cb1.z, cb1.w};
#pragma unroll
            for (int j = 0; j < 8; j++) {
                const int s = s0 + sseg + j;
                float v = 0.f;
                if (s <= l0 + lrow) v = cbv[j] * __expf(dacl - sdAc[s]);
                sbuf[YD_M + lrow * 40 + sseg + j] = __float2half_rn(v);
            }
        }
#pragma unroll
        for (int t = 0; t < 2; t++) {
            const int gi = t * 256 + tid;
            const int row = gi >> 4, p4 = (gi & 15) * 4;
            const float wv = sdtv[s0 + row];
            float4 v = *(const float4*)&g_conv[(size_t)(c * CH_ + s0 + row) * CONVD_ + h * HD_ + p4];
            uint32_t* d_ = (uint32_t*)&sbuf[YD_X + row * 72 + p4];
            d_[0] = pack2h(v.x * wv, v.y * wv);
            d_[1] = pack2h(v.z * wv, v.w * wv);
        }
        __syncthreads();
#pragma unroll
        for (int k16 = 0; k16 < 2; k16++) {
            uint32_t a[2][4];
#pragma unroll
            for (int mt = 0; mt < 2; mt++)
                LDSM4(a[mt], su32(&sbuf[YD_M + (warpM * 32 + mt * 16 + lr) * 40 + k16 * 16 + lc8]));
            uint32_t b[2][2];
            {
                const int nc = warpN * 16 + nbB;
                uint32_t r[4];
                LDSM4T(r, su32(&sbuf[YD_X + (k16 * 16 + krB) * 72 + nc]));
                b[0][0] = r[0]; b[0][1] = r[1]; b[1][0] = r[2]; b[1][1] = r[3];
            }
#pragma unroll
            for (int mt = 0; mt < 2; mt++)
#pragma unroll
                for (int ng = 0; ng < 2; ng++)
                    MMA16816H(accA[mt][ng], a[mt], b[ng][0], b[ng][1]);
        }
        __syncthreads();
    }

    const size_t pbase = ((size_t)(c * NH_ + h)) * HD_ * NST_;
    for (int n0c = 0; n0c < NST_; n0c += 64) {
#pragma unroll
        for (int t = 0; t < 4; t++) {
            const int gi = t * 256 + tid;
            const int row = gi >> 4, n4 = (gi & 15) * 4;
            float4 v = *(const float4*)&g_conv[(size_t)(c * CH_ + l0 + row) * CONVD_ +
                                               HID_ + NST_ + n0c + n4];
            uint32_t* d_ = (uint32_t*)&sbuf[YD_C + row * 72 + n4];
            d_[0] = pack2h(v.x, v.y);
            d_[1] = pack2h(v.z, v.w);

            float4 p = *(const float4*)&g_prev[pbase + (size_t)row * NST_ + n0c + n4];
            uint32_t* p_ = (uint32_t*)&sbuf[YD_P + row * 72 + n4];
            p_[0] = pack2h(p.x, p.y);
            p_[1] = pack2h(p.z, p.w);
        }
        __syncthreads();
#pragma unroll
        for (int k16 = 0; k16 < 4; k16++) {
            uint32_t a[2][4];
#pragma unroll
            for (int mt = 0; mt < 2; mt++)
                LDSM4(a[mt], su32(&sbuf[YD_C + (warpM * 32 + mt * 16 + lr) * 72 + k16 * 16 + lc8]));
            uint32_t b[4];
            LDSM4(b, su32(&sbuf[YD_P + (warpN * 16 + lr) * 72 + k16 * 16 + lc8]));
#pragma unroll
            for (int mt = 0; mt < 2; mt++)
#pragma unroll
                for (int ng = 0; ng < 2; ng++)
                    MMA16816H(acc2[mt][ng], a[mt], b[ng], b[ng + 2]);
        }
        __syncthreads();
    }

    const float dh = Dp[h];
#pragma unroll
    for (int mt = 0; mt < 2; mt++) {
        const int lrow = warpM * 32 + mt * 16 + (lane >> 2);
#pragma unroll
        for (int ng = 0; ng < 2; ng++) {
            const int col = warpN * 16 + ng * 8 + (lane & 3) * 2;
#pragma unroll
            for (int half = 0; half < 2; half++) {
                const int l = l0 + lrow + half * 8;
                const int t = c * CH_ + l;
                const float el = __expf(sdAc[l]);
                const float2 x2 = *(const float2*)&g_conv[(size_t)t * CONVD_ + h * HD_ + col];
                float2 o;
                o.x = accA[mt][ng][half * 2]     + el * acc2[mt][ng][half * 2]     + x2.x * dh;
                o.y = accA[mt][ng][half * 2 + 1] + el * acc2[mt][ng][half * 2 + 1] + x2.y * dh;
                *(float2*)&g_y[(size_t)t * HID_ + h * HD_ + col] = o;
            }
        }
    }
}

// ---------------------------------------------------------------------------
// gate + RMSNorm, fused fp16 output for out_proj
// ---------------------------------------------------------------------------
__global__ __launch_bounds__(256) void gatenorm_kernel(const float* __restrict__ nw)
{
    const int t = blockIdx.x;
    const int tid = threadIdx.x;
    float vals[16];
    float ss = 0.f;
#pragma unroll
    for (int k = 0; k < 16; k++) {
        const int i = tid + k * 256;
        const float yv = g_y[(size_t)t * HID_ + i];
        const float zv = g_zx[(size_t)t * D_IN_ + i];
        const float v = yv * (zv / (1.f + __expf(-zv)));
        vals[k] = v;
        ss += v * v;
    }
    __shared__ float red[8];
#pragma unroll
    for (int o = 16; o > 0; o >>= 1) ss += __shfl_xor_sync(0xffffffffu, ss, o);
    if ((tid & 31) == 0) red[tid >> 5] = ss;
    __syncthreads();
    if (tid < 8) {
        float v = red[tid];
#pragma unroll
        for (int o = 4; o > 0; o >>= 1) v += __shfl_xor_sync(0xffu, v, o);
        if (tid == 0) red[0] = v;
    }
    __syncthreads();
    const float scale = rsqrtf(red[0] / (float)HID_ + 1e-5f);
#pragma unroll
    for (int k = 0; k < 16; k++) {
        const int i = tid + k * 256;
        g_yh[(size_t)t * HID_ + i] = __float2half_rn(vals[k] * scale * nw[i]);
    }
}

// ---------------------------------------------------------------------------
extern "C" void kernel_launch(void* const* d_in, const int* in_sizes, int n_in,
                              void* d_out, int out_size)
{
    const float* x       = (const float*)d_in[0];
    const float* in_w    = (const float*)d_in[1];
    const float* conv_w  = (const float*)d_in[2];
    const float* dt_bias = (const float*)d_in[3];
    const float* A_log   = (const float*)d_in[4];
    const float* Dp      = (const float*)d_in[5];
    const float* norm_w  = (const float*)d_in[6];
    const float* out_w   = (const float*)d_in[7];
    float* out = (float*)d_out;

    float *zx, *conv, *cb;
    __half *xh, *wih, *yh, *woh;
    cudaGetSymbolAddress((void**)&zx, g_zx);
    cudaGetSymbolAddress((void**)&conv, g_conv);
    cudaGetSymbolAddress((void**)&cb, g_CB);
    cudaGetSymbolAddress((void**)&xh, g_xh);
    cudaGetSymbolAddress((void**)&wih, g_wih);
    cudaGetSymbolAddress((void**)&yh, g_yh);
    cudaGetSymbolAddress((void**)&woh, g_woh);

    cudaFuncSetAttribute(gemm_mma, cudaFuncAttributeMaxDynamicSharedMemorySize,
                         GM_SMEM_TOTAL);

    // 0) fp16 rounds for in_proj operands
    {
        const int n4s = S_LEN * DIM_ / 4;
        round_f16<<<(n4s + 255) / 256, 256>>>(x, xh, n4s, n4s);
        const int n4w = D_IN_ * DIM_ / 4;
        const int n4wt = D_INP_ * DIM_ / 4;
        round_f16<<<(n4wt + 255) / 256, 256>>>(in_w, wih, n4w, n4wt);
    }

    // 1) in_proj
    gemm_mma<<<dim3(D_INP_ / 128, S_LEN / 128), 256, GM_SMEM_TOTAL>>>(
        xh, wih, zx, D_IN_, DIM_);

    // 2) conv1d + SiLU (time-tiled)
    conv_silu_kernel<<<((S_LEN / CT_T) * (CONVD_ / 4) + 255) / 256, 256>>>(conv_w);

    // 3+4) fused dt + cumsum
    dtcumsum_kernel<<<dim3(NC_, NH_), CH_>>>(dt_bias, A_log);

    // 5) CB per chunk
    gemm128<<<dim3(2, 2, NC_), 256>>>(
        CH_, CH_, NST_,
        conv + HID_ + NST_, CONVD_, CH_ * CONVD_,
        conv + HID_,        CONVD_, CH_ * CONVD_,
        cb, CH_, CH_ * CH_);

    // 6) states (fp16 mma)
    states_mma<<<dim3(NC_, NH_), 256>>>();

    // 7) inter-chunk scan
    chunkscan_kernel<<<(NH_ * HD_ * NST_) / 256, 256>>>();

    // 8) y_diag + y_off + D-skip (fp16 mma)
    ydiag_mma<<<dim3(4, NC_, NH_), 256>>>(Dp);

    // 9) gate + RMSNorm (+ fused fp16 round)
    gatenorm_kernel<<<S_LEN, 256>>>(norm_w);

    // 10) out_proj
    {
        const int n4o = DIM_ * HID_ / 4;
        round_f16<<<(n4o + 255) / 256, 256>>>(out_w, woh, n4o, n4o);
    }
    gemm_mma<<<dim3(DIM_ / 128, S_LEN / 128), 256, GM_SMEM_TOTAL>>>(
        yh, woh, out, DIM_, HID_);
}